// round 16
// baseline (speedup 1.0000x reference)
#include <cuda_runtime.h>
#include <cuda_bf16.h>
#include <cuda_fp16.h>
#include <math.h>
#include <stdint.h>

// Problem constants
#define C_DIM 2048
#define N_EXP 64
#define MAX_N 16384
#define TMB 64                     // tokens per GEMM/hist tile
#define MAX_NB (MAX_N / TMB)       // 256
#define BKC 64                     // k per chunk (rows of 64 fp16 = 128 B)
#define NCHUNK (C_DIM / BKC)       // 32

// ---------------- scratch (device globals; no allocation allowed) -------------
__device__ int   g_top1[MAX_N];
__device__ int   g_top2[MAX_N];
__device__ float g_p1[MAX_N];
__device__ float g_p2[MAX_N];
__device__ int   g_hist0[MAX_NB * N_EXP];
__device__ int   g_hist1[MAX_NB * N_EXP];
__device__ int   g_off0[MAX_NB * N_EXP];
__device__ int   g_off1[MAX_NB * N_EXP];
__device__ __half g_wsp[2][N_EXP * C_DIM];   // w split hi/lo (fp16 2-level)

__device__ __forceinline__ uint32_t cvta_smem(const void* p) {
    uint32_t a;
    asm("{ .reg .u64 t; cvta.to.shared.u64 t, %1; cvt.u32.u64 %0, t; }"
        : "=r"(a) : "l"(p));
    return a;
}

// ---------------- K0: split w into hi/lo fp16 --------------------------------
__global__ void k_wsplit(const float* __restrict__ w) {
    int e = blockIdx.x;
    int t = threadIdx.x;
#pragma unroll
    for (int i = 0; i < C_DIM / 256; i++) {
        int k = t + i * 256;
        float v = w[(size_t)e * C_DIM + k];
        __half h = __float2half(v);
        float r = v - __half2float(h);
        __half m = __float2half(r);
        g_wsp[0][(size_t)e * C_DIM + k] = h;
        g_wsp[1][(size_t)e * C_DIM + k] = m;
    }
}

// ---------------- K1: HMMA fp16 3-term GEMM, 3 CTAs/SM + fused epilogue ------
// One block per 64-token tile; 8 warps in 4(M)x2(N) grid: 16 tok x 32 exp each.
// Terms: hh, hm, mh (mm dropped: <= 2^-22 relative).
// Per buffer: A 2 x 64 x 128B = 16 KB, B 2 x 64 x 128B = 16 KB -> 32 KB.
// 64 KB/CTA -> 3 CTAs/SM (192 <= 228 KB); regs must stay <= 85.
#define SM_BUF   32768               // 32 KB per buffer
#define SM_B_IN  16384               // B offset inside a buffer
#define SM_TOTAL (2 * SM_BUF)        // 64 KB

__global__ __launch_bounds__(256, 3)
void k_gemm_mma(const float* __restrict__ x) {
    extern __shared__ char smem[];
    const uint32_t sb = cvta_smem(smem);
    const int tid = threadIdx.x;
    const int wid = tid >> 5;
    const int lane = tid & 31;
    const int b = blockIdx.x;
    const int block_t0 = b * TMB;

    __shared__ int h0[N_EXP], h1[N_EXP];
    if (tid < N_EXP) { h0[tid] = 0; h1[tid] = 0; }

    const int wm = wid >> 1;        // 0..3 -> token rows wm*16
    const int wn = wid & 1;         // 0..1 -> expert cols wn*32
    const int R = wm * 16;
    const int Ecol = wn * 32;

    float acc[4][4];                // [n-tile][quad]
#pragma unroll
    for (int nt = 0; nt < 4; nt++)
#pragma unroll
        for (int q = 0; q < 4; q++) acc[nt][q] = 0.0f;

    // direct gmem->split->smem A store (no reg prefetch; latency hidden by co-CTAs)
    auto sstoreA = [&](int c, int buf) {
        char* base = smem + buf * SM_BUF;
#pragma unroll
        for (int i = 0; i < 2; i++) {
            int u = tid + i * 256;          // 0..511
            int r = u >> 3, cu = u & 7;
            const float* src = x + (size_t)(block_t0 + r) * C_DIM + c * BKC + cu * 8;
            float4 va = *(const float4*)src;
            float4 vb = *(const float4*)(src + 4);
            float2 f[4] = {
                make_float2(va.x, va.y), make_float2(va.z, va.w),
                make_float2(vb.x, vb.y), make_float2(vb.z, vb.w)};
            uint32_t ph[4], pm[4];
#pragma unroll
            for (int j = 0; j < 4; j++) {
                __half2 h2 = __float22half2_rn(f[j]);
                float2 back = __half22float2(h2);
                __half2 m2 = __float22half2_rn(make_float2(f[j].x - back.x,
                                                           f[j].y - back.y));
                ph[j] = *(uint32_t*)&h2;
                pm[j] = *(uint32_t*)&m2;
            }
            uint32_t dst = (uint32_t)(r * 128 + ((cu ^ (r & 7)) << 4));
            *(uint4*)(base + 0 * 8192 + dst) = make_uint4(ph[0], ph[1], ph[2], ph[3]);
            *(uint4*)(base + 1 * 8192 + dst) = make_uint4(pm[0], pm[1], pm[2], pm[3]);
        }
    };

    auto cpasyncB = [&](int c, int buf) {
        uint32_t bb = sb + buf * SM_BUF + SM_B_IN;
#pragma unroll
        for (int i = 0; i < 4; i++) {
            int u = tid + i * 256;          // 0..1023
            int l = u >> 9;                 // level 0..1
            int r = u & 511;
            int e = r >> 3, cu = r & 7;
            const void* src = &g_wsp[l][(size_t)e * C_DIM + c * BKC + cu * 8];
            uint32_t dst = bb + (uint32_t)(l * 8192 + e * 128 + ((cu ^ (e & 7)) << 4));
            asm volatile("cp.async.cg.shared.global [%0], [%1], 16;"
                         :: "r"(dst), "l"(src));
        }
        asm volatile("cp.async.commit_group;");
    };

    // ---- prologue: fill buffer 0 ----
    cpasyncB(0, 0);
    sstoreA(0, 0);
    asm volatile("cp.async.wait_group 0;");
    __syncthreads();

    for (int c = 0; c < NCHUNK; c++) {
        const int buf = c & 1;
        const uint32_t abase = sb + buf * SM_BUF;
        const uint32_t bbase = abase + SM_B_IN;

        if (c + 1 < NCHUNK) cpasyncB(c + 1, buf ^ 1);

        // ---- fragment-hoisted: per ks load 2 A-levels + 2 B-levels, 12 MMAs ----
#pragma unroll
        for (int ks = 0; ks < 4; ks++) {
            uint32_t ra[2][4];
#pragma unroll
            for (int lvl = 0; lvl < 2; lvl++) {
                int row = R + (lane & 15);
                int unit = ks * 2 + (lane >> 4);
                uint32_t addr = abase + lvl * 8192 + row * 128 + ((unit ^ (row & 7)) << 4);
                asm volatile(
                    "ldmatrix.sync.aligned.m8n8.x4.shared.b16 {%0,%1,%2,%3}, [%4];"
                    : "=r"(ra[lvl][0]), "=r"(ra[lvl][1]),
                      "=r"(ra[lvl][2]), "=r"(ra[lvl][3])
                    : "r"(addr));
            }
            uint32_t rb[2][4][2];
#pragma unroll
            for (int lvl = 0; lvl < 2; lvl++)
#pragma unroll
                for (int ntp = 0; ntp < 2; ntp++) {
                    int grp = lane >> 3;
                    int nt_sel = grp >> 1;
                    int k_sel = grp & 1;
                    int n = Ecol + ntp * 16 + nt_sel * 8 + (lane & 7);
                    int unit = ks * 2 + k_sel;
                    uint32_t addr = bbase + lvl * 8192 + n * 128 + ((unit ^ (n & 7)) << 4);
                    uint32_t q0, q1, q2, q3;
                    asm volatile(
                        "ldmatrix.sync.aligned.m8n8.x4.shared.b16 {%0,%1,%2,%3}, [%4];"
                        : "=r"(q0), "=r"(q1), "=r"(q2), "=r"(q3)
                        : "r"(addr));
                    rb[lvl][ntp * 2 + 0][0] = q0; rb[lvl][ntp * 2 + 0][1] = q1;
                    rb[lvl][ntp * 2 + 1][0] = q2; rb[lvl][ntp * 2 + 1][1] = q3;
                }

            // 3 cross terms: (a_lvl, b_lvl) = (0,0),(0,1),(1,0)
            const int ta[3] = {0, 0, 1};
            const int tb[3] = {0, 1, 0};
#pragma unroll
            for (int t = 0; t < 3; t++)
#pragma unroll
                for (int nt = 0; nt < 4; nt++) {
                    asm volatile(
                        "mma.sync.aligned.m16n8k16.row.col.f32.f16.f16.f32 "
                        "{%0,%1,%2,%3}, {%4,%5,%6,%7}, {%8,%9}, {%0,%1,%2,%3};"
                        : "+f"(acc[nt][0]), "+f"(acc[nt][1]),
                          "+f"(acc[nt][2]), "+f"(acc[nt][3])
                        : "r"(ra[ta[t]][0]), "r"(ra[ta[t]][1]),
                          "r"(ra[ta[t]][2]), "r"(ra[ta[t]][3]),
                          "r"(rb[tb[t]][nt][0]), "r"(rb[tb[t]][nt][1]));
                }
        }

        __syncthreads();                           // A/B(buf) consumed
        if (c + 1 < NCHUNK) sstoreA(c + 1, buf ^ 1);
        asm volatile("cp.async.wait_group 0;");
        __syncthreads();
    }

    // ---- epilogue: stage logits (reuse smem), top-2 + softmax + hist ----
    float* lg = (float*)smem;            // [64][65]
    const int LGS = 65;
#pragma unroll
    for (int nt = 0; nt < 4; nt++) {
        int r0 = R + (lane >> 2);
        int c0 = Ecol + nt * 8 + (lane & 3) * 2;
        lg[r0 * LGS + c0]           = acc[nt][0];
        lg[r0 * LGS + c0 + 1]       = acc[nt][1];
        lg[(r0 + 8) * LGS + c0]     = acc[nt][2];
        lg[(r0 + 8) * LGS + c0 + 1] = acc[nt][3];
    }
    __syncthreads();

    if (tid < TMB) {
        const float* row = &lg[tid * LGS];
        float b1 = -INFINITY, b2 = -INFINITY;
        int i1 = 0, i2 = 0;
#pragma unroll 8
        for (int e = 0; e < N_EXP; e++) {
            float v = row[e];
            if (v > b1) { b2 = b1; i2 = i1; b1 = v; i1 = e; }
            else if (v > b2) { b2 = v; i2 = e; }
        }
        float e2 = expf(b2 - b1);
        float inv = 1.0f / (1.0f + e2);
        int n = block_t0 + tid;
        g_top1[n] = i1; g_top2[n] = i2;
        g_p1[n] = inv;  g_p2[n] = e2 * inv;
        atomicAdd(&h0[i1], 1);
        atomicAdd(&h1[i2], 1);
    }
    __syncthreads();
    if (tid < N_EXP) {
        g_hist0[b * N_EXP + tid] = h0[tid];
        g_hist1[b * N_EXP + tid] = h1[tid];
    }
}

// ---------------- K2: parallel per-expert prefix over tiles ------------------
#define QPT (MAX_NB / 32)   // 8

__global__ void k_prefix(int NB) {
    const int e = blockIdx.x;
    const int lane = threadIdx.x;
    const int base = lane * QPT;

    int v[QPT];
#pragma unroll
    for (int q = 0; q < QPT; q++)
        v[q] = (base + q < NB) ? g_hist0[(base + q) * N_EXP + e] : 0;
    int s = 0;
#pragma unroll
    for (int q = 0; q < QPT; q++) s += v[q];
    int incl = s;
#pragma unroll
    for (int d = 1; d < 32; d <<= 1) {
        int t = __shfl_up_sync(0xffffffffu, incl, d);
        if (lane >= d) incl += t;
    }
    int run = incl - s;
#pragma unroll
    for (int q = 0; q < QPT; q++) {
        if (base + q < NB) g_off0[(base + q) * N_EXP + e] = run;
        run += v[q];
    }
    int total0 = __shfl_sync(0xffffffffu, incl, 31);

#pragma unroll
    for (int q = 0; q < QPT; q++)
        v[q] = (base + q < NB) ? g_hist1[(base + q) * N_EXP + e] : 0;
    s = 0;
#pragma unroll
    for (int q = 0; q < QPT; q++) s += v[q];
    incl = s;
#pragma unroll
    for (int d = 1; d < 32; d <<= 1) {
        int t = __shfl_up_sync(0xffffffffu, incl, d);
        if (lane >= d) incl += t;
    }
    run = total0 + (incl - s);
#pragma unroll
    for (int q = 0; q < QPT; q++) {
        if (base + q < NB) g_off1[(base + q) * N_EXP + e] = run;
        run += v[q];
    }
}

// ---------------- K3: ranks via match_any, capacity mask, all outputs --------
// 256 threads: warps 0-1 own the 64 tokens (match_any full-warp), all 8 warps
// share the vectorized mask-slab loop (float4 per lane, 8 rows/warp).
__global__ void k_final(int N, int cap, float* __restrict__ out, long out_elems) {
    __shared__ int s1[TMB], s2[TMB], r0[TMB], r1[TMB];
    __shared__ int wh0[2][N_EXP], wh1[2][N_EXP];

    const int tid = threadIdx.x;
    const int b = blockIdx.x;
    const int warp = tid >> 5;
    const int lane = tid & 31;
    const int n = b * TMB + tid;

    if (tid < 128) {
        (&wh0[0][0])[tid] = 0;
        (&wh1[0][0])[tid] = 0;
    }

    int e1 = 0, e2v = 0;
    float p1v = 0.f, p2v = 0.f;
    if (tid < TMB) {
        e1  = g_top1[n];
        e2v = g_top2[n];
        p1v = g_p1[n];
        p2v = g_p2[n];
        s1[tid] = e1; s2[tid] = e2v;
    }
    __syncthreads();

    int rw0 = 0, rw1 = 0;
    if (tid < TMB) {
        unsigned lt = (1u << lane) - 1u;
        unsigned m0 = __match_any_sync(0xffffffffu, e1);
        rw0 = __popc(m0 & lt);
        if (rw0 == 0) wh0[warp][e1] = __popc(m0);
        unsigned m1 = __match_any_sync(0xffffffffu, e2v);
        rw1 = __popc(m1 & lt);
        if (rw1 == 0) wh1[warp][e2v] = __popc(m1);
    }
    __syncthreads();

    // output layout (float32 elements):
    //   [0, N*128) mask | [N*128,+2N) probs | [+2N) idx | [+2N) rank | [1] cap
    const size_t off_probs = (size_t)N * 128;
    const size_t off_idx   = off_probs + (size_t)N * 2;
    const size_t off_rank  = off_idx + (size_t)N * 2;
    const size_t off_cap   = off_rank + (size_t)N * 2;

    if (tid < TMB) {
        int rr0 = g_off0[b * N_EXP + e1]  + rw0 + (warp ? wh0[0][e1]  : 0);
        int rr1 = g_off1[b * N_EXP + e2v] + rw1 + (warp ? wh1[0][e2v] : 0);
        r0[tid] = rr0; r1[tid] = rr1;

        size_t p;
        p = off_idx + (size_t)n * 2;
        if (p + 1 < (size_t)out_elems) { out[p] = (float)e1; out[p + 1] = (float)e2v; }
        p = off_rank + (size_t)n * 2;
        if (p + 1 < (size_t)out_elems) { out[p] = (float)rr0; out[p + 1] = (float)rr1; }
        p = off_probs + (size_t)n * 2;
        if (p + 1 < (size_t)out_elems) {
            out[p]     = (rr0 < cap) ? p1v : 0.0f;
            out[p + 1] = (rr1 < cap) ? p2v : 0.0f;
        }
    }
    if (b == 0 && tid == 0 && off_cap < (size_t)out_elems) out[off_cap] = (float)cap;
    __syncthreads();

    // mask slab: lane writes float4 (4 expert cols) of one token row; 8 warps
    const int e_base = lane * 4;
    for (int i = warp; i < TMB; i += 8) {
        float4 v;
        if (lane < 16) {
            int s = s1[i]; bool ok = r0[i] < cap;
            v.x = (ok && s == e_base + 0) ? 1.0f : 0.0f;
            v.y = (ok && s == e_base + 1) ? 1.0f : 0.0f;
            v.z = (ok && s == e_base + 2) ? 1.0f : 0.0f;
            v.w = (ok && s == e_base + 3) ? 1.0f : 0.0f;
        } else {
            int s = s2[i] + 64; bool ok = r1[i] < cap;
            v.x = (ok && s == e_base + 0) ? 1.0f : 0.0f;
            v.y = (ok && s == e_base + 1) ? 1.0f : 0.0f;
            v.z = (ok && s == e_base + 2) ? 1.0f : 0.0f;
            v.w = (ok && s == e_base + 3) ? 1.0f : 0.0f;
        }
        size_t pos = (size_t)(b * TMB + i) * 128 + e_base;
        if (pos + 3 < (size_t)out_elems) *(float4*)&out[pos] = v;
    }
}

// ---------------- launch ------------------------------------------------------
extern "C" void kernel_launch(void* const* d_in, const int* in_sizes, int n_in,
                              void* d_out, int out_size) {
    const float* x = (const float*)d_in[0];
    const float* w = (const float*)d_in[1];
    int N = in_sizes[0] / C_DIM;              // 16384
    if (N > MAX_N) N = MAX_N;

    int cap = (int)((2.0 * 2.0 * (double)N) / 64.0);
    if (cap < 4) cap = 4;

    int NB = N / TMB;                         // 256

    cudaFuncSetAttribute(k_gemm_mma, cudaFuncAttributeMaxDynamicSharedMemorySize, SM_TOTAL);

    k_wsplit<<<N_EXP, 256>>>(w);
    k_gemm_mma<<<NB, 256, SM_TOTAL>>>(x);
    k_prefix<<<N_EXP, 32>>>(NB);
    k_final<<<NB, 256>>>(N, cap, (float*)d_out, (long)out_size);
}

// round 17
// speedup vs baseline: 1.1366x; 1.1366x over previous
#include <cuda_runtime.h>
#include <cuda_bf16.h>
#include <cuda_fp16.h>
#include <math.h>
#include <stdint.h>

// Problem constants
#define C_DIM 2048
#define N_EXP 64
#define MAX_N 16384
#define TMB 64                     // tokens per GEMM/hist tile
#define MAX_NB (MAX_N / TMB)       // 256
#define BKC 64                     // k per chunk (rows of 64 fp16 = 128 B)
#define NCHUNK (C_DIM / BKC)       // 32

// ---------------- scratch (device globals; no allocation allowed) -------------
__device__ int   g_top1[MAX_N];
__device__ int   g_top2[MAX_N];
__device__ float g_p1[MAX_N];
__device__ float g_p2[MAX_N];
__device__ int   g_hist0[MAX_NB * N_EXP];
__device__ int   g_hist1[MAX_NB * N_EXP];
__device__ int   g_off0[MAX_NB * N_EXP];
__device__ int   g_off1[MAX_NB * N_EXP];
__device__ __half g_wsp[2][N_EXP * C_DIM];   // w split hi/lo (fp16 2-level)

__device__ __forceinline__ uint32_t cvta_smem(const void* p) {
    uint32_t a;
    asm("{ .reg .u64 t; cvta.to.shared.u64 t, %1; cvt.u32.u64 %0, t; }"
        : "=r"(a) : "l"(p));
    return a;
}

// ---------------- K0: split w into hi/lo fp16 --------------------------------
__global__ void k_wsplit(const float* __restrict__ w) {
    int e = blockIdx.x;
    int t = threadIdx.x;
#pragma unroll
    for (int i = 0; i < C_DIM / 256; i++) {
        int k = t + i * 256;
        float v = w[(size_t)e * C_DIM + k];
        __half h = __float2half(v);
        float r = v - __half2float(h);
        __half m = __float2half(r);
        g_wsp[0][(size_t)e * C_DIM + k] = h;
        g_wsp[1][(size_t)e * C_DIM + k] = m;
    }
}

// ---------------- K1: HMMA fp16 3-term GEMM, 2 CTAs/SM + fused epilogue ------
// VERBATIM from the round-15 66.3us pass.
// One block per 64-token tile; 8 warps in 4(M)x2(N) grid: 16 tok x 32 exp each.
// Terms: hh, hm, mh (mm dropped: <= 2^-22 relative).
#define SM_BUF   32768               // 32 KB per buffer
#define SM_B_IN  16384               // B offset inside a buffer
#define SM_TOTAL (2 * SM_BUF)        // 64 KB -> 2 CTAs/SM

__global__ __launch_bounds__(256, 2)
void k_gemm_mma(const float* __restrict__ x) {
    extern __shared__ char smem[];
    const uint32_t sb = cvta_smem(smem);
    const int tid = threadIdx.x;
    const int wid = tid >> 5;
    const int lane = tid & 31;
    const int b = blockIdx.x;
    const int block_t0 = b * TMB;

    __shared__ int h0[N_EXP], h1[N_EXP];
    if (tid < N_EXP) { h0[tid] = 0; h1[tid] = 0; }

    const int wm = wid >> 1;        // 0..3 -> token rows wm*16
    const int wn = wid & 1;         // 0..1 -> expert cols wn*32
    const int R = wm * 16;
    const int Ecol = wn * 32;

    float acc[4][4];                // [n-tile][quad]
#pragma unroll
    for (int nt = 0; nt < 4; nt++)
#pragma unroll
        for (int q = 0; q < 4; q++) acc[nt][q] = 0.0f;

    float4 xva[2], xvb[2];          // A prefetch registers (2 units/thread)

    auto gloadA = [&](int c) {
#pragma unroll
        for (int i = 0; i < 2; i++) {
            int u = tid + i * 256;          // 0..511
            int r = u >> 3, cu = u & 7;
            const float* src = x + (size_t)(block_t0 + r) * C_DIM + c * BKC + cu * 8;
            xva[i] = *(const float4*)src;
            xvb[i] = *(const float4*)(src + 4);
        }
    };

    // packed-RN fp16 split (identical numerics to scalar __float2half path)
    auto sstoreA = [&](int buf) {
        char* base = smem + buf * SM_BUF;
#pragma unroll
        for (int i = 0; i < 2; i++) {
            int u = tid + i * 256;
            int r = u >> 3, cu = u & 7;
            float2 f[4] = {
                make_float2(xva[i].x, xva[i].y), make_float2(xva[i].z, xva[i].w),
                make_float2(xvb[i].x, xvb[i].y), make_float2(xvb[i].z, xvb[i].w)};
            uint32_t ph[4], pm[4];
#pragma unroll
            for (int j = 0; j < 4; j++) {
                __half2 h2 = __float22half2_rn(f[j]);
                float2 back = __half22float2(h2);
                __half2 m2 = __float22half2_rn(make_float2(f[j].x - back.x,
                                                           f[j].y - back.y));
                ph[j] = *(uint32_t*)&h2;
                pm[j] = *(uint32_t*)&m2;
            }
            uint32_t dst = (uint32_t)(r * 128 + ((cu ^ (r & 7)) << 4));
            *(uint4*)(base + 0 * 8192 + dst) = make_uint4(ph[0], ph[1], ph[2], ph[3]);
            *(uint4*)(base + 1 * 8192 + dst) = make_uint4(pm[0], pm[1], pm[2], pm[3]);
        }
    };

    auto cpasyncB = [&](int c, int buf) {
        uint32_t bb = sb + buf * SM_BUF + SM_B_IN;
#pragma unroll
        for (int i = 0; i < 4; i++) {
            int u = tid + i * 256;          // 0..1023
            int l = u >> 9;                 // level 0..1
            int r = u & 511;
            int e = r >> 3, cu = r & 7;
            const void* src = &g_wsp[l][(size_t)e * C_DIM + c * BKC + cu * 8];
            uint32_t dst = bb + (uint32_t)(l * 8192 + e * 128 + ((cu ^ (e & 7)) << 4));
            asm volatile("cp.async.cg.shared.global [%0], [%1], 16;"
                         :: "r"(dst), "l"(src));
        }
        asm volatile("cp.async.commit_group;");
    };

    // ---- prologue: fill buffer 0 ----
    gloadA(0);
    cpasyncB(0, 0);
    sstoreA(0);
    asm volatile("cp.async.wait_group 0;");
    __syncthreads();

    for (int c = 0; c < NCHUNK; c++) {
        const int buf = c & 1;
        const uint32_t abase = sb + buf * SM_BUF;
        const uint32_t bbase = abase + SM_B_IN;

        if (c + 1 < NCHUNK) {
            gloadA(c + 1);
            cpasyncB(c + 1, buf ^ 1);
        }

        // ---- fragment-hoisted: per ks load 2 A-levels + 2 B-levels, 12 MMAs ----
#pragma unroll
        for (int ks = 0; ks < 4; ks++) {
            uint32_t ra[2][4];
#pragma unroll
            for (int lvl = 0; lvl < 2; lvl++) {
                int row = R + (lane & 15);
                int unit = ks * 2 + (lane >> 4);
                uint32_t addr = abase + lvl * 8192 + row * 128 + ((unit ^ (row & 7)) << 4);
                asm volatile(
                    "ldmatrix.sync.aligned.m8n8.x4.shared.b16 {%0,%1,%2,%3}, [%4];"
                    : "=r"(ra[lvl][0]), "=r"(ra[lvl][1]),
                      "=r"(ra[lvl][2]), "=r"(ra[lvl][3])
                    : "r"(addr));
            }
            uint32_t rb[2][4][2];
#pragma unroll
            for (int lvl = 0; lvl < 2; lvl++)
#pragma unroll
                for (int ntp = 0; ntp < 2; ntp++) {
                    int grp = lane >> 3;
                    int nt_sel = grp >> 1;
                    int k_sel = grp & 1;
                    int n = Ecol + ntp * 16 + nt_sel * 8 + (lane & 7);
                    int unit = ks * 2 + k_sel;
                    uint32_t addr = bbase + lvl * 8192 + n * 128 + ((unit ^ (n & 7)) << 4);
                    uint32_t q0, q1, q2, q3;
                    asm volatile(
                        "ldmatrix.sync.aligned.m8n8.x4.shared.b16 {%0,%1,%2,%3}, [%4];"
                        : "=r"(q0), "=r"(q1), "=r"(q2), "=r"(q3)
                        : "r"(addr));
                    rb[lvl][ntp * 2 + 0][0] = q0; rb[lvl][ntp * 2 + 0][1] = q1;
                    rb[lvl][ntp * 2 + 1][0] = q2; rb[lvl][ntp * 2 + 1][1] = q3;
                }

            // 3 cross terms: (a_lvl, b_lvl) = (0,0),(0,1),(1,0)
            const int ta[3] = {0, 0, 1};
            const int tb[3] = {0, 1, 0};
#pragma unroll
            for (int t = 0; t < 3; t++)
#pragma unroll
                for (int nt = 0; nt < 4; nt++) {
                    asm volatile(
                        "mma.sync.aligned.m16n8k16.row.col.f32.f16.f16.f32 "
                        "{%0,%1,%2,%3}, {%4,%5,%6,%7}, {%8,%9}, {%0,%1,%2,%3};"
                        : "+f"(acc[nt][0]), "+f"(acc[nt][1]),
                          "+f"(acc[nt][2]), "+f"(acc[nt][3])
                        : "r"(ra[ta[t]][0]), "r"(ra[ta[t]][1]),
                          "r"(ra[ta[t]][2]), "r"(ra[ta[t]][3]),
                          "r"(rb[tb[t]][nt][0]), "r"(rb[tb[t]][nt][1]));
                }
        }

        if (c + 1 < NCHUNK) sstoreA(buf ^ 1);   // convert under tensor shadow
        asm volatile("cp.async.wait_group 0;");
        __syncthreads();
    }

    // ---- epilogue: stage logits (reuse smem), top-2 + softmax + hist ----
    float* lg = (float*)smem;            // [64][65]
    const int LGS = 65;
#pragma unroll
    for (int nt = 0; nt < 4; nt++) {
        int r0 = R + (lane >> 2);
        int c0 = Ecol + nt * 8 + (lane & 3) * 2;
        lg[r0 * LGS + c0]           = acc[nt][0];
        lg[r0 * LGS + c0 + 1]       = acc[nt][1];
        lg[(r0 + 8) * LGS + c0]     = acc[nt][2];
        lg[(r0 + 8) * LGS + c0 + 1] = acc[nt][3];
    }
    __syncthreads();

    if (tid < TMB) {
        const float* row = &lg[tid * LGS];
        float b1 = -INFINITY, b2 = -INFINITY;
        int i1 = 0, i2 = 0;
#pragma unroll 8
        for (int e = 0; e < N_EXP; e++) {
            float v = row[e];
            if (v > b1) { b2 = b1; i2 = i1; b1 = v; i1 = e; }
            else if (v > b2) { b2 = v; i2 = e; }
        }
        float e2 = expf(b2 - b1);
        float inv = 1.0f / (1.0f + e2);
        int n = block_t0 + tid;
        g_top1[n] = i1; g_top2[n] = i2;
        g_p1[n] = inv;  g_p2[n] = e2 * inv;
        atomicAdd(&h0[i1], 1);
        atomicAdd(&h1[i2], 1);
    }
    __syncthreads();
    if (tid < N_EXP) {
        g_hist0[b * N_EXP + tid] = h0[tid];
        g_hist1[b * N_EXP + tid] = h1[tid];
    }
}

// ---------------- K2: parallel per-expert prefix over tiles ------------------
#define QPT (MAX_NB / 32)   // 8

__global__ void k_prefix(int NB) {
    const int e = blockIdx.x;
    const int lane = threadIdx.x;
    const int base = lane * QPT;

    int v[QPT];
#pragma unroll
    for (int q = 0; q < QPT; q++)
        v[q] = (base + q < NB) ? g_hist0[(base + q) * N_EXP + e] : 0;
    int s = 0;
#pragma unroll
    for (int q = 0; q < QPT; q++) s += v[q];
    int incl = s;
#pragma unroll
    for (int d = 1; d < 32; d <<= 1) {
        int t = __shfl_up_sync(0xffffffffu, incl, d);
        if (lane >= d) incl += t;
    }
    int run = incl - s;
#pragma unroll
    for (int q = 0; q < QPT; q++) {
        if (base + q < NB) g_off0[(base + q) * N_EXP + e] = run;
        run += v[q];
    }
    int total0 = __shfl_sync(0xffffffffu, incl, 31);

#pragma unroll
    for (int q = 0; q < QPT; q++)
        v[q] = (base + q < NB) ? g_hist1[(base + q) * N_EXP + e] : 0;
    s = 0;
#pragma unroll
    for (int q = 0; q < QPT; q++) s += v[q];
    incl = s;
#pragma unroll
    for (int d = 1; d < 32; d <<= 1) {
        int t = __shfl_up_sync(0xffffffffu, incl, d);
        if (lane >= d) incl += t;
    }
    run = total0 + (incl - s);
#pragma unroll
    for (int q = 0; q < QPT; q++) {
        if (base + q < NB) g_off1[(base + q) * N_EXP + e] = run;
        run += v[q];
    }
}

// ---------------- K3: ranks via match_any, capacity mask, all outputs --------
// VERBATIM from the round-16 pass (6.8us). 256 threads: warps 0-1 own the 64
// tokens; all 8 warps share the vectorized float4 mask loop.
__global__ void k_final(int N, int cap, float* __restrict__ out, long out_elems) {
    __shared__ int s1[TMB], s2[TMB], r0[TMB], r1[TMB];
    __shared__ int wh0[2][N_EXP], wh1[2][N_EXP];

    const int tid = threadIdx.x;
    const int b = blockIdx.x;
    const int warp = tid >> 5;
    const int lane = tid & 31;
    const int n = b * TMB + tid;

    if (tid < 128) {
        (&wh0[0][0])[tid] = 0;
        (&wh1[0][0])[tid] = 0;
    }

    int e1 = 0, e2v = 0;
    float p1v = 0.f, p2v = 0.f;
    if (tid < TMB) {
        e1  = g_top1[n];
        e2v = g_top2[n];
        p1v = g_p1[n];
        p2v = g_p2[n];
        s1[tid] = e1; s2[tid] = e2v;
    }
    __syncthreads();

    int rw0 = 0, rw1 = 0;
    if (tid < TMB) {
        unsigned lt = (1u << lane) - 1u;
        unsigned m0 = __match_any_sync(0xffffffffu, e1);
        rw0 = __popc(m0 & lt);
        if (rw0 == 0) wh0[warp][e1] = __popc(m0);
        unsigned m1 = __match_any_sync(0xffffffffu, e2v);
        rw1 = __popc(m1 & lt);
        if (rw1 == 0) wh1[warp][e2v] = __popc(m1);
    }
    __syncthreads();

    // output layout (float32 elements):
    //   [0, N*128) mask | [N*128,+2N) probs | [+2N) idx | [+2N) rank | [1] cap
    const size_t off_probs = (size_t)N * 128;
    const size_t off_idx   = off_probs + (size_t)N * 2;
    const size_t off_rank  = off_idx + (size_t)N * 2;
    const size_t off_cap   = off_rank + (size_t)N * 2;

    if (tid < TMB) {
        int rr0 = g_off0[b * N_EXP + e1]  + rw0 + (warp ? wh0[0][e1]  : 0);
        int rr1 = g_off1[b * N_EXP + e2v] + rw1 + (warp ? wh1[0][e2v] : 0);
        r0[tid] = rr0; r1[tid] = rr1;

        size_t p;
        p = off_idx + (size_t)n * 2;
        if (p + 1 < (size_t)out_elems) { out[p] = (float)e1; out[p + 1] = (float)e2v; }
        p = off_rank + (size_t)n * 2;
        if (p + 1 < (size_t)out_elems) { out[p] = (float)rr0; out[p + 1] = (float)rr1; }
        p = off_probs + (size_t)n * 2;
        if (p + 1 < (size_t)out_elems) {
            out[p]     = (rr0 < cap) ? p1v : 0.0f;
            out[p + 1] = (rr1 < cap) ? p2v : 0.0f;
        }
    }
    if (b == 0 && tid == 0 && off_cap < (size_t)out_elems) out[off_cap] = (float)cap;
    __syncthreads();

    // mask slab: lane writes float4 (4 expert cols) of one token row; 8 warps
    const int e_base = lane * 4;
    for (int i = warp; i < TMB; i += 8) {
        float4 v;
        if (lane < 16) {
            int s = s1[i]; bool ok = r0[i] < cap;
            v.x = (ok && s == e_base + 0) ? 1.0f : 0.0f;
            v.y = (ok && s == e_base + 1) ? 1.0f : 0.0f;
            v.z = (ok && s == e_base + 2) ? 1.0f : 0.0f;
            v.w = (ok && s == e_base + 3) ? 1.0f : 0.0f;
        } else {
            int s = s2[i] + 64; bool ok = r1[i] < cap;
            v.x = (ok && s == e_base + 0) ? 1.0f : 0.0f;
            v.y = (ok && s == e_base + 1) ? 1.0f : 0.0f;
            v.z = (ok && s == e_base + 2) ? 1.0f : 0.0f;
            v.w = (ok && s == e_base + 3) ? 1.0f : 0.0f;
        }
        size_t pos = (size_t)(b * TMB + i) * 128 + e_base;
        if (pos + 3 < (size_t)out_elems) *(float4*)&out[pos] = v;
    }
}

// ---------------- launch ------------------------------------------------------
extern "C" void kernel_launch(void* const* d_in, const int* in_sizes, int n_in,
                              void* d_out, int out_size) {
    const float* x = (const float*)d_in[0];
    const float* w = (const float*)d_in[1];
    int N = in_sizes[0] / C_DIM;              // 16384
    if (N > MAX_N) N = MAX_N;

    int cap = (int)((2.0 * 2.0 * (double)N) / 64.0);
    if (cap < 4) cap = 4;

    int NB = N / TMB;                         // 256

    cudaFuncSetAttribute(k_gemm_mma, cudaFuncAttributeMaxDynamicSharedMemorySize, SM_TOTAL);

    k_wsplit<<<N_EXP, 256>>>(w);
    k_gemm_mma<<<NB, 256, SM_TOTAL>>>(x);
    k_prefix<<<N_EXP, 32>>>(NB);
    k_final<<<NB, 256>>>(N, cap, (float*)d_out, (long)out_size);
}